// round 16
// baseline (speedup 1.0000x reference)
#include <cuda_runtime.h>
#include <cuda_fp16.h>
#include <cstdint>

#define Bsz 8
#define NSEQ 1024
#define OUTD 1024
#define DHD 128

#define DINLINE __device__ __forceinline__

// ---------------- scratch (allocation-free rule: __device__ globals) ----------
__device__ __align__(16) __half h_kv [8u*1024u*2048u];   // src_trans half [B*NS,2048]
__device__ __align__(16) __half h_q  [8u*1024u*1024u];   // tgt_trans half
__device__ __align__(16) __half h_upd[8u*1024u*1024u];   // tgt_update half
__device__ __align__(16) __half h_src[8u*1024u*1024u];   // fp16 inputs
__device__ __align__(16) __half h_tgt[8u*1024u*1024u];
__device__ __align__(16) __half h_ws [2u*1024u*1024u];
__device__ __align__(16) __half h_wt [1024u*1024u];
__device__ __align__(16) __half h_wo [2u*1024u*1024u];

// ---------------- helpers ------------------------------------------------------
DINLINE uint32_t smem_u32(const void* p) {
    uint32_t a;
    asm("{ .reg .u64 t; cvta.to.shared.u64 t, %1; cvt.u32.u64 %0, t; }" : "=r"(a) : "l"(p));
    return a;
}
DINLINE void cp16(uint32_t dst, const void* src) {
    asm volatile("cp.async.cg.shared.global [%0], [%1], 16;" :: "r"(dst), "l"(src) : "memory");
}
DINLINE void cp_commit() { asm volatile("cp.async.commit_group;" ::: "memory"); }
DINLINE void cp_wait0()  { asm volatile("cp.async.wait_group 0;" ::: "memory"); }
DINLINE void cp_wait1()  { asm volatile("cp.async.wait_group 1;" ::: "memory"); }
DINLINE void cp_wait2()  { asm volatile("cp.async.wait_group 2;" ::: "memory"); }

DINLINE void mma_h(float c[4], const uint32_t a[4], const uint32_t b[2]) {
    asm volatile(
        "mma.sync.aligned.m16n8k16.row.col.f32.f16.f16.f32 "
        "{%0,%1,%2,%3}, {%4,%5,%6,%7}, {%8,%9}, {%0,%1,%2,%3};"
        : "+f"(c[0]), "+f"(c[1]), "+f"(c[2]), "+f"(c[3])
        : "r"(a[0]), "r"(a[1]), "r"(a[2]), "r"(a[3]), "r"(b[0]), "r"(b[1]));
}

DINLINE void ldsm_x4(uint32_t& r0, uint32_t& r1, uint32_t& r2, uint32_t& r3, uint32_t a) {
    asm volatile("ldmatrix.sync.aligned.m8n8.x4.shared.b16 {%0,%1,%2,%3}, [%4];"
                 : "=r"(r0), "=r"(r1), "=r"(r2), "=r"(r3) : "r"(a));
}
DINLINE void ldsm_x4_t(uint32_t& r0, uint32_t& r1, uint32_t& r2, uint32_t& r3, uint32_t a) {
    asm volatile("ldmatrix.sync.aligned.m8n8.x4.trans.shared.b16 {%0,%1,%2,%3}, [%4];"
                 : "=r"(r0), "=r"(r1), "=r"(r2), "=r"(r3) : "r"(a));
}

DINLINE uint32_t ldh2(const __half* p) { return *(const uint32_t*)p; }
DINLINE uint32_t packh2(float x, float y) {
    __half2 h = __floats2half2_rn(x, y);
    return *reinterpret_cast<uint32_t*>(&h);
}

// ================================================================================
// single-launch f32 -> fp16 conversion, MLP-8: each thread resolves 4 strided
// uint4 chunks, batches all 8 float4 loads before any store.
// ================================================================================
__global__ void f2h_all(const float4* __restrict__ i0, uint4* __restrict__ o0, int n0,
                        const float4* __restrict__ i1, uint4* __restrict__ o1, int n1,
                        const float4* __restrict__ i2, uint4* __restrict__ o2, int n2,
                        const float4* __restrict__ i3, uint4* __restrict__ o3, int n3,
                        const float4* __restrict__ i4, uint4* __restrict__ o4, int n4)
{
    const int t = blockIdx.x * blockDim.x + threadIdx.x;
    const int stride = gridDim.x * blockDim.x;

    const float4* ip[4];
    uint4* op[4];
    int li[4];
    bool act[4];
#pragma unroll
    for (int r = 0; r < 4; r++) {
        int i = t + r * stride;
        act[r] = true;
        if (i < n0)                          { ip[r] = i0; op[r] = o0; li[r] = i; }
        else { i -= n0; if (i < n1)          { ip[r] = i1; op[r] = o1; li[r] = i; }
        else { i -= n1; if (i < n2)          { ip[r] = i2; op[r] = o2; li[r] = i; }
        else { i -= n2; if (i < n3)          { ip[r] = i3; op[r] = o3; li[r] = i; }
        else { i -= n3; if (i < n4)          { ip[r] = i4; op[r] = o4; li[r] = i; }
        else act[r] = false; } } } }
    }

    float4 a[4], b[4];
#pragma unroll
    for (int r = 0; r < 4; r++)
        if (act[r]) { a[r] = ip[r][2 * li[r]]; b[r] = ip[r][2 * li[r] + 1]; }

#pragma unroll
    for (int r = 0; r < 4; r++) {
        if (act[r]) {
            uint4 o;
            o.x = packh2(a[r].x, a[r].y);
            o.y = packh2(a[r].z, a[r].w);
            o.z = packh2(b[r].x, b[r].y);
            o.w = packh2(b[r].z, b[r].w);
            op[r][li[r]] = o;
        }
    }
}

// ================================================================================
// fp16 GEMM body (R10-proven): BM=BN=128, BK=32, 4 warps 64x64, ldmatrix.x4,
// 4-stage cp.async, single __syncthreads per k-block. outHalf: 1=fp16, 0=f32.
// ================================================================================
#define GS 4
#define STGH (2 * 128 * 40)
#define STGB (STGH * 2)

DINLINE void gemm_body(const __half* __restrict__ A0, const __half* __restrict__ A1,
                       const __half* __restrict__ W, int ldw,
                       const float* __restrict__ bias, const float* __restrict__ rowmask,
                       void* __restrict__ Cv, int ldc, int nkb, int outHalf,
                       int mBase, int nBase, __half* smh)
{
    const uint32_t sb = smem_u32(smh);

    const int tid  = threadIdx.x;
    const int lane = tid & 31;
    const int wid  = tid >> 5;
    const int wm   = wid & 1;
    const int wn   = wid >> 1;
    const int g    = lane >> 2;
    const int tg   = lane & 3;

    uint32_t dOf[4];
    int aOf[4], wOf[4];
#pragma unroll
    for (int i = 0; i < 4; i++) {
        int idx = tid + i * 128;
        int row = idx >> 2, c = idx & 3;
        dOf[i] = row * 80 + c * 16;
        aOf[i] = (mBase + row) * 1024 + c * 8;
        wOf[i] = (nBase + row) * ldw + c * 8;
    }

    auto ISSUE = [&](int kb) {
        const int s = kb & 3;
        const int kg = kb * 32;
        const __half* Ap = (kg < 1024) ? A0 : A1;
        const int ka = kg & 1023;
        const uint32_t sa  = sb + s * STGB;
        const uint32_t sbb = sa + 128 * 80;
#pragma unroll
        for (int i = 0; i < 4; i++) cp16(sa  + dOf[i], Ap + aOf[i] + ka);
#pragma unroll
        for (int i = 0; i < 4; i++) cp16(sbb + dOf[i], W  + wOf[i] + kg);
        cp_commit();
    };

    const uint32_t aLn = (lane & 15) * 80 + ((lane & 16) ? 16u : 0u);
    const uint32_t bLn = (lane & 7) * 80 + ((lane & 16) ? 8u * 80u : 0u) + ((lane & 8) ? 16u : 0u);

    float acc[4][8][4];
#pragma unroll
    for (int mt = 0; mt < 4; mt++)
#pragma unroll
        for (int nt = 0; nt < 8; nt++)
#pragma unroll
            for (int i = 0; i < 4; i++) acc[mt][nt][i] = 0.f;

    ISSUE(0); ISSUE(1); ISSUE(2);

    for (int kb = 0; kb < nkb; kb++) {
        if (kb < nkb - 2)      cp_wait2();
        else if (kb < nkb - 1) cp_wait1();
        else                   cp_wait0();
        __syncthreads();
        if (kb + 3 < nkb) ISSUE(kb + 3);

        const uint32_t saA = sb + (kb & 3) * STGB;
        const uint32_t saB = saA + 128 * 80;
#pragma unroll
        for (int ks = 0; ks < 2; ks++) {
            const uint32_t aBase = saA + (uint32_t)(wm * 64) * 80 + ks * 32 + aLn;
            const uint32_t bBase = saB + (uint32_t)(wn * 64) * 80 + ks * 32 + bLn;
            uint32_t af[4][4], bf[8][2];
#pragma unroll
            for (int mt = 0; mt < 4; mt++)
                ldsm_x4(af[mt][0], af[mt][1], af[mt][2], af[mt][3], aBase + mt * 16 * 80);
#pragma unroll
            for (int p = 0; p < 4; p++)
                ldsm_x4(bf[2*p][0], bf[2*p][1], bf[2*p+1][0], bf[2*p+1][1], bBase + p * 16 * 80);
#pragma unroll
            for (int mt = 0; mt < 4; mt++)
#pragma unroll
                for (int nt = 0; nt < 8; nt++)
                    mma_h(acc[mt][nt], af[mt], bf[nt]);
        }
    }

#pragma unroll
    for (int mt = 0; mt < 4; mt++) {
        int r0 = mBase + wm * 64 + mt * 16 + g;
        float mk0 = rowmask ? rowmask[r0]     : 1.f;
        float mk1 = rowmask ? rowmask[r0 + 8] : 1.f;
#pragma unroll
        for (int nt = 0; nt < 8; nt++) {
            int c = nBase + wn * 64 + nt * 8 + 2 * tg;
            float b0 = bias ? bias[c]     : 0.f;
            float b1 = bias ? bias[c + 1] : 0.f;
            float v00 = (acc[mt][nt][0] + b0) * mk0;
            float v01 = (acc[mt][nt][1] + b1) * mk0;
            float v10 = (acc[mt][nt][2] + b0) * mk1;
            float v11 = (acc[mt][nt][3] + b1) * mk1;
            if (outHalf) {
                __half* Ch = (__half*)Cv;
                *(uint32_t*)(Ch + (size_t)r0 * ldc + c)       = packh2(v00, v01);
                *(uint32_t*)(Ch + (size_t)(r0 + 8) * ldc + c) = packh2(v10, v11);
            } else {
                float* Cf = (float*)Cv;
                *(float2*)(Cf + (size_t)r0 * ldc + c)       = make_float2(v00, v01);
                *(float2*)(Cf + (size_t)(r0 + 8) * ldc + c) = make_float2(v10, v11);
            }
        }
    }
}

// out-GEMM (fused K=2048 concat)
__global__ __launch_bounds__(128, 2)
void gemm_h(const __half* __restrict__ A0, const __half* __restrict__ A1,
            const __half* __restrict__ W, int ldw,
            const float* __restrict__ bias, const float* __restrict__ rowmask,
            void* __restrict__ Cv, int ldc, int nkb, int outHalf)
{
    extern __shared__ __half smh[];
    gemm_body(A0, A1, W, ldw, bias, rowmask, Cv, ldc, nkb, outHalf,
              blockIdx.y * 128, blockIdx.x * 128, smh);
}

// merged projection GEMMs: x<16 -> kv (N=2048), x>=16 -> q (N=1024)
__global__ __launch_bounds__(128, 2)
void gemm12_h(const __half* __restrict__ Asrc, const __half* __restrict__ Ws_,
              const float* __restrict__ bs_, const float* __restrict__ smask,
              __half* __restrict__ kv,
              const __half* __restrict__ Atgt, const __half* __restrict__ Wt_,
              const float* __restrict__ bt_, const float* __restrict__ tmask,
              __half* __restrict__ q)
{
    extern __shared__ __half smh[];
    if (blockIdx.x < 16)
        gemm_body(Asrc, Asrc, Ws_, 1024, bs_, smask, kv, 2048, 32, 1,
                  blockIdx.y * 128, blockIdx.x * 128, smh);
    else
        gemm_body(Atgt, Atgt, Wt_, 1024, bt_, tmask, q, 1024, 32, 1,
                  blockIdx.y * 128, (blockIdx.x - 16) * 128, smh);
}

// ================================================================================
// fp16 flash attention — VERBATIM R15 (proven): BM=64, 128 threads, 2 CTAs/SM,
// P in regs, Q in smem via ldmatrix, exp2 softmax.
// smem (halves): Q[64][136] | K[2][64][136] | V[2][64][136] | f32 mask[2][64]
// ================================================================================
#define QH  (64 * 136)
#define KST (64 * 136)
#define VST (64 * 136)
#define KOFF QH
#define VOFF (QH + 2 * KST)
#define MBYTE ((VOFF + 2 * VST) * 2)
#define ATTN_SMEMB (MBYTE + 2 * 64 * 4)

__global__ __launch_bounds__(128, 2)
void attn_h(const __half* __restrict__ Q, const __half* __restrict__ KV,
            const float* __restrict__ smask, __half* __restrict__ O)
{
    extern __shared__ __half smh[];
    const uint32_t sb = smem_u32(smh);

    const int tid  = threadIdx.x;
    const int lane = tid & 31;
    const int w    = tid >> 5;
    const int g    = lane >> 2;
    const int tg   = lane & 3;

    const int bh = blockIdx.y;
    const int b  = bh >> 3;
    const int hh = bh & 7;
    const int t0 = blockIdx.x * 64;

    const __half* qg = Q + ((size_t)b * NSEQ + t0) * OUTD + hh * DHD;
    const __half* kg = KV + (size_t)b * NSEQ * (2 * OUTD) + hh * DHD;
    const __half* vg = kg + OUTD;
    const float*  mg = smask + (size_t)b * NSEQ;

#pragma unroll
    for (int i = 0; i < 8; i++) {
        int idx = tid + i * 128;
        int row = idx >> 4, c8 = idx & 15;
        cp16(sb + (row * 136 + c8 * 8) * 2, qg + (size_t)row * OUTD + c8 * 8);
    }
    cp_commit();

    auto ISSUE = [&](int j) {
        const int st = j & 1;
#pragma unroll
        for (int i = 0; i < 8; i++) {
            int idx = tid + i * 128;
            int row = idx >> 4, c = idx & 15;
            size_t go = (size_t)(j * 64 + row) * (2 * OUTD) + c * 8;
            cp16(sb + (KOFF + st * KST + row * 136 + c * 8) * 2, kg + go);
            cp16(sb + (VOFF + st * VST + row * 136 + c * 8) * 2, vg + go);
        }
        if (tid < 16)
            cp16(sb + MBYTE + st * 256 + tid * 16, mg + j * 64 + tid * 4);
        cp_commit();
    };

    float oacc[16][4];
#pragma unroll
    for (int nt = 0; nt < 16; nt++)
#pragma unroll
        for (int i = 0; i < 4; i++) oacc[nt][i] = 0.f;
    float m0 = -1e30f, m1 = -1e30f, l0 = 0.f, l1 = 0.f;

    const float sc2 = 0.12756277212531545f;  // (1/sqrt(128)) * log2(e)
    const int vlane = (lane & 15) * 136 + ((lane & 16) ? 8 : 0);
    const uint32_t kLn = (lane & 7) * 272 + ((lane & 16) ? 8u * 272u : 0u) + ((lane & 8) ? 16u : 0u);
    const uint32_t qLn = (lane & 15) * 272 + ((lane & 16) ? 16u : 0u);
    const uint32_t qbase = sb + (uint32_t)(w * 16) * 272;

    ISSUE(0);

    for (int j = 0; j < NSEQ / 64; j++) {
        const int st = j & 1;
        cp_wait0();
        __syncthreads();
        if (j + 1 < NSEQ / 64) ISSUE(j + 1);

        const float*  msk = (const float*)((const char*)smh + MBYTE + st * 256);
        const uint32_t kbase = sb + (KOFF + st * KST) * 2;
        const uint32_t vbase = sb + (VOFF + st * VST) * 2;

        float sacc[8][4];
#pragma unroll
        for (int nt = 0; nt < 8; nt++)
#pragma unroll
            for (int i = 0; i < 4; i++) sacc[nt][i] = 0.f;

#pragma unroll
        for (int ks = 0; ks < 8; ks++) {
            uint32_t qa[4];
            ldsm_x4(qa[0], qa[1], qa[2], qa[3], qbase + ks * 32 + qLn);
            const uint32_t bBase = kbase + ks * 32 + kLn;
            uint32_t bf[8][2];
#pragma unroll
            for (int p = 0; p < 4; p++)
                ldsm_x4(bf[2*p][0], bf[2*p][1], bf[2*p+1][0], bf[2*p+1][1], bBase + p * 16 * 272);
#pragma unroll
            for (int nt = 0; nt < 8; nt++)
                mma_h(sacc[nt], qa, bf[nt]);
        }

        float rmax0 = -1e30f, rmax1 = -1e30f;
#pragma unroll
        for (int nt = 0; nt < 8; nt++) {
#pragma unroll
            for (int i = 0; i < 4; i++) {
                float sv = sacc[nt][i] * sc2;
                int col = nt * 8 + 2 * tg + (i & 1);
                if (msk[col] == 0.f) sv = -1e30f;
                sacc[nt][i] = sv;
                if (i < 2) rmax0 = fmaxf(rmax0, sv);
                else       rmax1 = fmaxf(rmax1, sv);
            }
        }
        rmax0 = fmaxf(rmax0, __shfl_xor_sync(0xffffffffu, rmax0, 1));
        rmax0 = fmaxf(rmax0, __shfl_xor_sync(0xffffffffu, rmax0, 2));
        rmax1 = fmaxf(rmax1, __shfl_xor_sync(0xffffffffu, rmax1, 1));
        rmax1 = fmaxf(rmax1, __shfl_xor_sync(0xffffffffu, rmax1, 2));

        float mn0 = fmaxf(m0, rmax0), mn1 = fmaxf(m1, rmax1);
        float cf0 = exp2f(m0 - mn0), cf1 = exp2f(m1 - mn1);
        m0 = mn0; m1 = mn1;

        uint32_t pp[8][2];
        float rs0 = 0.f, rs1 = 0.f;
#pragma unroll
        for (int nt = 0; nt < 8; nt++) {
            float p0 = exp2f(sacc[nt][0] - mn0);
            float p1 = exp2f(sacc[nt][1] - mn0);
            float p2 = exp2f(sacc[nt][2] - mn1);
            float p3 = exp2f(sacc[nt][3] - mn1);
            rs0 += p0 + p1; rs1 += p2 + p3;
            pp[nt][0] = packh2(p0, p1);
            pp[nt][1] = packh2(p2, p3);
        }
        rs0 += __shfl_xor_sync(0xffffffffu, rs0, 1);
        rs0 += __shfl_xor_sync(0xffffffffu, rs0, 2);
        rs1 += __shfl_xor_sync(0xffffffffu, rs1, 1);
        rs1 += __shfl_xor_sync(0xffffffffu, rs1, 2);
        l0 = l0 * cf0 + rs0;
        l1 = l1 * cf1 + rs1;

#pragma unroll
        for (int nt = 0; nt < 16; nt++) {
            oacc[nt][0] *= cf0; oacc[nt][1] *= cf0;
            oacc[nt][2] *= cf1; oacc[nt][3] *= cf1;
        }

#pragma unroll
        for (int ks = 0; ks < 4; ks++) {
            uint32_t pa[4];
            pa[0] = pp[2 * ks][0];
            pa[1] = pp[2 * ks][1];
            pa[2] = pp[2 * ks + 1][0];
            pa[3] = pp[2 * ks + 1][1];
            const uint32_t vrow = vbase + (ks * 16 * 136 + vlane) * 2;
#pragma unroll
            for (int dg = 0; dg < 8; dg++) {
                uint32_t r0, r1, r2, r3;
                ldsm_x4_t(r0, r1, r2, r3, vrow + dg * 32);
                uint32_t b0[2] = {r0, r1}, b1[2] = {r2, r3};
                mma_h(oacc[2 * dg],     pa, b0);
                mma_h(oacc[2 * dg + 1], pa, b1);
            }
        }
    }

    float inv0 = 1.f / l0, inv1 = 1.f / l1;
    const int tr0 = t0 + w * 16 + g;
    __half* og = O + (size_t)b * NSEQ * OUTD + hh * DHD;
#pragma unroll
    for (int nt = 0; nt < 16; nt++) {
        int dc = nt * 8 + 2 * tg;
        *(uint32_t*)(og + (size_t)tr0 * OUTD + dc) =
            packh2(oacc[nt][0] * inv0, oacc[nt][1] * inv0);
        *(uint32_t*)(og + (size_t)(tr0 + 8) * OUTD + dc) =
            packh2(oacc[nt][2] * inv1, oacc[nt][3] * inv1);
    }
}

// ================================================================================
// launch
// ================================================================================
extern "C" void kernel_launch(void* const* d_in, const int* in_sizes, int n_in,
                              void* d_out, int out_size)
{
    const float* src      = (const float*)d_in[0];
    const float* tgt      = (const float*)d_in[1];
    const float* src_mask = (const float*)d_in[2];
    const float* tgt_mask = (const float*)d_in[3];
    const float* Ws       = (const float*)d_in[4];
    const float* bs       = (const float*)d_in[5];
    const float* Wt       = (const float*)d_in[6];
    const float* bt       = (const float*)d_in[7];
    const float* Wo       = (const float*)d_in[8];
    const float* bo       = (const float*)d_in[9];
    float* out = (float*)d_out;

    __half *kv, *q, *upd, *hsrc, *htgt, *hws, *hwt, *hwo;
    cudaGetSymbolAddress((void**)&kv,   h_kv);
    cudaGetSymbolAddress((void**)&q,    h_q);
    cudaGetSymbolAddress((void**)&upd,  h_upd);
    cudaGetSymbolAddress((void**)&hsrc, h_src);
    cudaGetSymbolAddress((void**)&htgt, h_tgt);
    cudaGetSymbolAddress((void**)&hws,  h_ws);
    cudaGetSymbolAddress((void**)&hwt,  h_wt);
    cudaGetSymbolAddress((void**)&hwo,  h_wo);

    const int gSmem = GS * STGB;               // 81920
    const int aSmem = ATTN_SMEMB;              // ~88KB
    cudaFuncSetAttribute(gemm_h,   cudaFuncAttributeMaxDynamicSharedMemorySize, gSmem);
    cudaFuncSetAttribute(gemm12_h, cudaFuncAttributeMaxDynamicSharedMemorySize, gSmem);
    cudaFuncSetAttribute(attn_h,   cudaFuncAttributeMaxDynamicSharedMemorySize, aSmem);

    // 0) single-launch f32 -> fp16 conversion, MLP-8 grid-stride
    const int nSrc = 8*1024*1024/8, nW2 = 2*1024*1024/8, nW1 = 1024*1024/8;
    const int nTot = 2 * nSrc + 2 * nW2 + nW1;          // 2,752,512 (divisible by 4)
    const int cvtThreads = nTot / 4;                     // 688,128
    f2h_all<<<cvtThreads / 256, 256>>>(
        (const float4*)src, (uint4*)hsrc, nSrc,
        (const float4*)tgt, (uint4*)htgt, nSrc,
        (const float4*)Ws,  (uint4*)hws,  nW2,
        (const float4*)Wt,  (uint4*)hwt,  nW1,
        (const float4*)Wo,  (uint4*)hwo,  nW2);

    const int M = Bsz * NSEQ; // 8192

    // 1+2) merged: kv = src@Ws^T+bs (*src_mask), q = tgt@Wt^T+bt (*tgt_mask)
    gemm12_h<<<dim3(24, M / 128), 128, gSmem>>>(
        hsrc, hws, bs, src_mask, kv,
        htgt, hwt, bt, tgt_mask, q);

    // 3) flash attention -> upd fp16       [8192, 1024]
    attn_h<<<dim3(NSEQ / 64, Bsz * 8), 128, aSmem>>>(q, kv, src_mask, upd);

    // 4) out = [tgt | upd] @ Wo^T + bo  (fused K=2048) -> f32
    gemm_h<<<dim3(1024 / 128, M / 128), 128, gSmem>>>(
        htgt, upd, hwo, 2048, bo, nullptr, out, 1024, 64, 0);
}